// round 10
// baseline (speedup 1.0000x reference)
#include <cuda_runtime.h>

// Fixed shapes from setup_inputs
#define LQ 512   // sequence length
#define DD 256   // per-tensor feature dim
#define FD 512   // 2*DD (MLP hidden)
#define NB 2     // batch
#define NH 8     // heads
#define DK 64    // head dim

// Scratch (no cudaMalloc allowed)
__device__ float g_A[NB * LQ * FD];   // d1 @ W1[:DD]
__device__ float g_C[NB * LQ * FD];   // d0 @ W1[DD:] + b1
__device__ float g_D[NB * LQ * LQ];   // decisions: 0 or -1e9

typedef unsigned long long u64;

// Packed f32x2 (sm_100+): 2 fp32 lanes per fma-pipe instruction.
#define FFMA2(d,a,b,c) asm("fma.rn.f32x2 %0,%1,%2,%3;" : "=l"(d) : "l"(a),"l"(b),"l"(c))
#define FADD2(d,a,b)   asm("add.rn.f32x2 %0,%1,%2;"    : "=l"(d) : "l"(a),"l"(b))

__device__ __forceinline__ float2 unpk(u64 p) {
    float lo, hi;
    asm("mov.b64 {%0,%1},%2;" : "=f"(lo), "=f"(hi) : "l"(p));
    return make_float2(lo, hi);
}

#define ABS2_MASK 0x7FFFFFFF7FFFFFFFULL     // |x| on both packed halves
#define EIGHTH2   0x3E0000003E000000ULL     // {0.125f, 0.125f}

// Thread mapping (all kernels): 256 threads, iy = t>>4 (0..15), jx = t&15.
// Per-thread 4i x 4j. Accumulators: acc[i][p] = packed pair over j (8 u64).
// A-side smem is PRE-DUPLICATED {a,a} -> inner-loop reads are 16-way
// broadcast LDS.128 (conflict-free) and feed FFMA2 directly (zero movs).
// B-side smem plain [k][j]; jx*4 floats = 16B lane stride (conflict-free).

// ---------------------------------------------------------------------------
// Kernel 1: A = d1 @ W1_top ; C = d0 @ W1_bot + b1   (M=1024, N=512, K=256)
// 64m x 64n tile, 256 threads, K-chunk 16. Grid 8 x 16 x 2 = 256 blocks.
// ---------------------------------------------------------------------------
__global__ __launch_bounds__(256) void gemm_ac_kernel(
    const float* __restrict__ d1, const float* __restrict__ d0,
    const float* __restrict__ W1, const float* __restrict__ b1)
{
    const int z = blockIdx.z;                       // 0 -> A, 1 -> C
    const float* __restrict__ src = z ? d0 : d1;    // [1024, 256]
    const float* __restrict__ W   = W1 + (z ? DD * FD : 0);  // [256, 512]
    float* dst = z ? g_C : g_A;

    __shared__ __align__(16) float As2[16 * 128];   // [k][2m] duplicated
    __shared__ __align__(16) float Bs[16 * 64];     // [k][n]

    const int m0 = blockIdx.y * 64, n0 = blockIdx.x * 64;
    const int t  = threadIdx.x;
    const int jx = t & 15, iy = t >> 4;
    const int ii = t >> 2, qq = t & 3;              // A fill: row ii, k-quad qq
    const int bk = t >> 4, nq = t & 15;             // B fill: k-row bk, n-quad nq

    u64 acc[4][2] = {};

    for (int k0 = 0; k0 < DD; k0 += 16) {
        __syncthreads();
        {
            float4 v = *(const float4*)&src[(m0 + ii) * DD + k0 + qq * 4];
            *(float2*)&As2[(qq * 4 + 0) * 128 + 2 * ii] = make_float2(v.x, v.x);
            *(float2*)&As2[(qq * 4 + 1) * 128 + 2 * ii] = make_float2(v.y, v.y);
            *(float2*)&As2[(qq * 4 + 2) * 128 + 2 * ii] = make_float2(v.z, v.z);
            *(float2*)&As2[(qq * 4 + 3) * 128 + 2 * ii] = make_float2(v.w, v.w);
            *(float4*)&Bs[bk * 64 + nq * 4] =
                *(const float4*)&W[(k0 + bk) * FD + n0 + nq * 4];
        }
        __syncthreads();

        #pragma unroll
        for (int kk = 0; kk < 16; kk++) {
            ulonglong2 aA = *(const ulonglong2*)&As2[kk * 128 + 8 * iy];
            ulonglong2 aB = *(const ulonglong2*)&As2[kk * 128 + 8 * iy + 4];
            ulonglong2 bp = *(const ulonglong2*)&Bs[kk * 64 + jx * 4];
            FFMA2(acc[0][0], aA.x, bp.x, acc[0][0]);
            FFMA2(acc[0][1], aA.x, bp.y, acc[0][1]);
            FFMA2(acc[1][0], aA.y, bp.x, acc[1][0]);
            FFMA2(acc[1][1], aA.y, bp.y, acc[1][1]);
            FFMA2(acc[2][0], aB.x, bp.x, acc[2][0]);
            FFMA2(acc[2][1], aB.x, bp.y, acc[2][1]);
            FFMA2(acc[3][0], aB.y, bp.x, acc[3][0]);
            FFMA2(acc[3][1], aB.y, bp.y, acc[3][1]);
        }
    }

    u64 bz0 = 0, bz1 = 0;
    if (z) {
        bz0 = *(const u64*)&b1[n0 + jx * 4];
        bz1 = *(const u64*)&b1[n0 + jx * 4 + 2];
    }

    #pragma unroll
    for (int i = 0; i < 4; i++) {
        ulonglong2 r;
        FADD2(r.x, acc[i][0], bz0);
        FADD2(r.y, acc[i][1], bz1);
        *(ulonglong2*)&dst[(m0 + iy * 4 + i) * FD + n0 + jx * 4] = r;
    }
}

// ---------------------------------------------------------------------------
// Kernel 2: decisions[b,i,j] = (sum_f relu(A[b,i,f]+C[b,j,f])*w2d[f] + b2d > 0)
//           ? -1e9 : 0
// 64i x 64j tile, 256 threads, f-chunk 32 with chunk-local partials (the
// two-level fp32 accumulation is precision-critical: margin flips are ~1e9
// each). relu via exact identity relu(s)*w = (s+|s|)*(w/2); |s| = and.b64.
// Grid 8 x 8 x 2 = 128 blocks.
// ---------------------------------------------------------------------------
__global__ __launch_bounds__(256) void decisions_kernel(
    const float* __restrict__ W2, const float* __restrict__ b2)
{
    const int b  = blockIdx.z;
    const int i0 = blockIdx.y * 64;
    const int j0 = blockIdx.x * 64;
    const float* __restrict__ Ab = g_A + b * LQ * FD;
    const float* __restrict__ Cb = g_C + b * LQ * FD;

    __shared__ __align__(16) float As2[32 * 128];   // [f][2i] duplicated
    __shared__ __align__(16) float Cs[32 * 64];     // [f][j]
    __shared__ __align__(16) float2 ws2[FD];        // {w/2, w/2}

    const int t  = threadIdx.x;
    const int jx = t & 15, iy = t >> 4;
    const int ii = t >> 2, qq = t & 3;              // fills: row ii, f-quad qq

    for (int f = t; f < FD; f += 256) {
        float w = 0.5f * (W2[2 * f + 1] - W2[2 * f]);
        ws2[f] = make_float2(w, w);
    }

    u64 acc[4][2] = {};

    for (int f0 = 0; f0 < FD; f0 += 32) {
        __syncthreads();
        #pragma unroll
        for (int h = 0; h < 2; h++) {
            int q = qq + h * 4;                     // 0..7 covers 32 f
            float4 v = *(const float4*)&Ab[(i0 + ii) * FD + f0 + q * 4];
            *(float2*)&As2[(q * 4 + 0) * 128 + 2 * ii] = make_float2(v.x, v.x);
            *(float2*)&As2[(q * 4 + 1) * 128 + 2 * ii] = make_float2(v.y, v.y);
            *(float2*)&As2[(q * 4 + 2) * 128 + 2 * ii] = make_float2(v.z, v.z);
            *(float2*)&As2[(q * 4 + 3) * 128 + 2 * ii] = make_float2(v.w, v.w);
            float4 c = *(const float4*)&Cb[(j0 + ii) * FD + f0 + q * 4];
            Cs[(q * 4 + 0) * 64 + ii] = c.x;
            Cs[(q * 4 + 1) * 64 + ii] = c.y;
            Cs[(q * 4 + 2) * 64 + ii] = c.z;
            Cs[(q * 4 + 3) * 64 + ii] = c.w;
        }
        __syncthreads();

        u64 accC[4][2] = {};
        #pragma unroll
        for (int kk = 0; kk < 32; kk++) {
            ulonglong2 aA = *(const ulonglong2*)&As2[kk * 128 + 8 * iy];
            ulonglong2 aB = *(const ulonglong2*)&As2[kk * 128 + 8 * iy + 4];
            ulonglong2 cp = *(const ulonglong2*)&Cs[kk * 64 + jx * 4];
            u64 wd = *(const u64*)&ws2[f0 + kk];
            u64 ad[4] = {aA.x, aA.y, aB.x, aB.y};
            #pragma unroll
            for (int i = 0; i < 4; i++) {
                u64 s, s2;
                FADD2(s, ad[i], cp.x);
                s2 = s & ABS2_MASK;                 // |s|
                FADD2(s2, s, s2);                   // 2*relu(s), exact
                FFMA2(accC[i][0], s2, wd, accC[i][0]);   // *(w/2): exact scale
                FADD2(s, ad[i], cp.y);
                s2 = s & ABS2_MASK;
                FADD2(s2, s, s2);
                FFMA2(accC[i][1], s2, wd, accC[i][1]);
            }
        }
        #pragma unroll
        for (int i = 0; i < 4; i++) {
            FADD2(acc[i][0], acc[i][0], accC[i][0]);
            FADD2(acc[i][1], acc[i][1], accC[i][1]);
        }
    }

    const float b2d = b2[1] - b2[0];
    float* Db = g_D + b * LQ * LQ;
    #pragma unroll
    for (int i = 0; i < 4; i++) {
        float2 p0 = unpk(acc[i][0]), p1 = unpk(acc[i][1]);
        float4 r = make_float4(
            (p0.x + b2d > 0.f) ? -1e9f : 0.f, (p0.y + b2d > 0.f) ? -1e9f : 0.f,
            (p1.x + b2d > 0.f) ? -1e9f : 0.f, (p1.y + b2d > 0.f) ? -1e9f : 0.f);
        *(float4*)&Db[(i0 + iy * 4 + i) * LQ + j0 + jx * 4] = r;
    }
}

// ---------------------------------------------------------------------------
// Kernel 3: out[b,n,i,j] = dot(q[b,n,i,:], k[b,n,j,:]) * 0.125 + D[b,i,j]
// 64i x 64j tile, 256 threads, full d=64 staged once (48KB smem).
// Grid 8 x 8 x 16 = 1024 blocks.
// ---------------------------------------------------------------------------
__global__ __launch_bounds__(256) void attn_kernel(
    const float* __restrict__ q, const float* __restrict__ k,
    float* __restrict__ out)
{
    const int bn = blockIdx.z;          // b*NH + n
    const int b  = bn >> 3;
    const int i0 = blockIdx.y * 64;
    const int j0 = blockIdx.x * 64;
    const float* __restrict__ Q = q + bn * LQ * DK;
    const float* __restrict__ K = k + bn * LQ * DK;

    __shared__ __align__(16) float Qs2[64 * 128];   // [d][2i] duplicated (32KB)
    __shared__ __align__(16) float Ks[64 * 64];     // [d][j] (16KB)

    const int t  = threadIdx.x;
    const int jx = t & 15, iy = t >> 4;
    const int ii = t >> 2, qq = t & 3;

    #pragma unroll
    for (int h = 0; h < 4; h++) {
        int d = (qq + h * 4) * 4;                   // 16 quads cover d=64
        float4 v = *(const float4*)&Q[(i0 + ii) * DK + d];
        *(float2*)&Qs2[(d + 0) * 128 + 2 * ii] = make_float2(v.x, v.x);
        *(float2*)&Qs2[(d + 1) * 128 + 2 * ii] = make_float2(v.y, v.y);
        *(float2*)&Qs2[(d + 2) * 128 + 2 * ii] = make_float2(v.z, v.z);
        *(float2*)&Qs2[(d + 3) * 128 + 2 * ii] = make_float2(v.w, v.w);
        float4 u = *(const float4*)&K[(j0 + ii) * DK + d];
        Ks[(d + 0) * 64 + ii] = u.x;
        Ks[(d + 1) * 64 + ii] = u.y;
        Ks[(d + 2) * 64 + ii] = u.z;
        Ks[(d + 3) * 64 + ii] = u.w;
    }
    __syncthreads();

    u64 acc[4][2] = {};
    #pragma unroll 16
    for (int dd = 0; dd < DK; dd++) {
        ulonglong2 aA = *(const ulonglong2*)&Qs2[dd * 128 + 8 * iy];
        ulonglong2 aB = *(const ulonglong2*)&Qs2[dd * 128 + 8 * iy + 4];
        ulonglong2 bp = *(const ulonglong2*)&Ks[dd * 64 + jx * 4];
        FFMA2(acc[0][0], aA.x, bp.x, acc[0][0]);
        FFMA2(acc[0][1], aA.x, bp.y, acc[0][1]);
        FFMA2(acc[1][0], aA.y, bp.x, acc[1][0]);
        FFMA2(acc[1][1], aA.y, bp.y, acc[1][1]);
        FFMA2(acc[2][0], aB.x, bp.x, acc[2][0]);
        FFMA2(acc[2][1], aB.x, bp.y, acc[2][1]);
        FFMA2(acc[3][0], aB.y, bp.x, acc[3][0]);
        FFMA2(acc[3][1], aB.y, bp.y, acc[3][1]);
    }

    const float* Db = g_D + b * LQ * LQ;
    float* O = out + bn * LQ * LQ;
    const u64 e2 = EIGHTH2;
    #pragma unroll
    for (int i = 0; i < 4; i++) {
        int row = i0 + iy * 4 + i;
        ulonglong2 dv = *(const ulonglong2*)&Db[row * LQ + j0 + jx * 4];
        ulonglong2 r;
        FFMA2(r.x, acc[i][0], e2, dv.x);            // qk*0.125 + D, packed
        FFMA2(r.y, acc[i][1], e2, dv.y);
        *(ulonglong2*)&O[row * LQ + j0 + jx * 4] = r;
    }
}

// ---------------------------------------------------------------------------
// Inputs (metadata order): q, k, d0, d1, W1, b1, W2, b2
// ---------------------------------------------------------------------------
extern "C" void kernel_launch(void* const* d_in, const int* in_sizes, int n_in,
                              void* d_out, int out_size)
{
    const float* q  = (const float*)d_in[0];   // [2,8,512,64]
    const float* k  = (const float*)d_in[1];   // [2,8,512,64]
    const float* d0 = (const float*)d_in[2];   // [2,512,256]
    const float* d1 = (const float*)d_in[3];   // [2,512,256]
    const float* W1 = (const float*)d_in[4];   // [512,512]
    const float* b1 = (const float*)d_in[5];   // [512]
    const float* W2 = (const float*)d_in[6];   // [512,2]
    const float* b2 = (const float*)d_in[7];   // [2]
    float* out = (float*)d_out;                // [2,8,512,512]

    (void)in_sizes; (void)n_in; (void)out_size;

    gemm_ac_kernel  <<<dim3(FD / 64, (NB * LQ) / 64, 2),   256>>>(d1, d0, W1, b1);
    decisions_kernel<<<dim3(LQ / 64, LQ / 64, NB),         256>>>(W2, b2);
    attn_kernel     <<<dim3(LQ / 64, LQ / 64, NB * NH),    256>>>(q, k, out);
}

// round 11
// speedup vs baseline: 1.1672x; 1.1672x over previous
#include <cuda_runtime.h>

// Fixed shapes from setup_inputs
#define LQ 512   // sequence length
#define DD 256   // per-tensor feature dim
#define FD 512   // 2*DD (MLP hidden)
#define NB 2     // batch
#define NH 8     // heads
#define DK 64    // head dim

// Scratch (no cudaMalloc allowed)
__device__ float g_A[NB * LQ * FD];   // d1 @ W1[:DD]
__device__ float g_C[NB * LQ * FD];   // d0 @ W1[DD:] + b1
__device__ float g_D[NB * LQ * LQ];   // decisions: 0 or -1e9

typedef unsigned long long u64;

// Packed f32x2 (sm_100+)
#define FFMA2(d,a,b,c) asm("fma.rn.f32x2 %0,%1,%2,%3;" : "=l"(d) : "l"(a),"l"(b),"l"(c))
#define FADD2(d,a,b)   asm("add.rn.f32x2 %0,%1,%2;"    : "=l"(d) : "l"(a),"l"(b))

__device__ __forceinline__ float2 unpk(u64 p) {
    float lo, hi;
    asm("mov.b64 {%0,%1},%2;" : "=f"(lo), "=f"(hi) : "l"(p));
    return make_float2(lo, hi);
}

#define ABS2_MASK 0x7FFFFFFF7FFFFFFFULL     // |x| on both packed halves
#define EIGHTH2   0x3E0000003E000000ULL     // {0.125f, 0.125f}

// Strides (floats). AP=132: dup-A rows rotate 4 banks/row (fill conflicts
// 2-way max), reads 16B-aligned (528 = 33*16). BP=68 (272 = 17*16). CP=34.
#define AP 132
#define BP 68
#define CP 34

// ---------------------------------------------------------------------------
// Kernel 1: A = d1 @ W1_top ; C = d0 @ W1_bot + b1   (M=1024, N=512, K=256)
// 64m x 64n, 256 threads, per-thread 4i x 4j (j-packed), K-chunk 16,
// 2-stage pipeline (prefetch LDG during compute, 1 barrier/chunk).
// Grid 8 x 16 x 2 = 256 blocks.
// ---------------------------------------------------------------------------
__global__ __launch_bounds__(256) void gemm_ac_kernel(
    const float* __restrict__ d1, const float* __restrict__ d0,
    const float* __restrict__ W1, const float* __restrict__ b1)
{
    const int z = blockIdx.z;
    const float* __restrict__ src = z ? d0 : d1;            // [1024, 256]
    const float* __restrict__ W   = W1 + (z ? DD * FD : 0); // [256, 512]
    float* dst = z ? g_C : g_A;

    __shared__ __align__(16) float As2[2][16 * AP];   // [k][2m] duplicated
    __shared__ __align__(16) float Bs[2][16 * BP];    // [k][n]

    const int m0 = blockIdx.y * 64, n0 = blockIdx.x * 64;
    const int t  = threadIdx.x;
    const int jx = t & 15, iy = t >> 4;
    const int rA = t >> 2, qA = t & 3;                // A fill: m-row, k-quad
    const int rB = t >> 4, qB = t & 15;               // B fill: k-row, n-quad

    u64 acc[4][2] = {};
    float4 va, vb;

    va = *(const float4*)&src[(m0 + rA) * DD + qA * 4];
    vb = *(const float4*)&W[rB * FD + n0 + qB * 4];

    #pragma unroll 1
    for (int c = 0; c < DD / 16; c++) {
        const int buf = c & 1;
        *(float2*)&As2[buf][(qA * 4 + 0) * AP + 2 * rA] = make_float2(va.x, va.x);
        *(float2*)&As2[buf][(qA * 4 + 1) * AP + 2 * rA] = make_float2(va.y, va.y);
        *(float2*)&As2[buf][(qA * 4 + 2) * AP + 2 * rA] = make_float2(va.z, va.z);
        *(float2*)&As2[buf][(qA * 4 + 3) * AP + 2 * rA] = make_float2(va.w, va.w);
        *(float4*)&Bs[buf][rB * BP + qB * 4] = vb;
        __syncthreads();

        if (c + 1 < DD / 16) {
            int k0 = (c + 1) * 16;
            va = *(const float4*)&src[(m0 + rA) * DD + k0 + qA * 4];
            vb = *(const float4*)&W[(k0 + rB) * FD + n0 + qB * 4];
        }

        #pragma unroll
        for (int kk = 0; kk < 16; kk++) {
            ulonglong2 aA = *(const ulonglong2*)&As2[buf][kk * AP + 8 * iy];
            ulonglong2 aB = *(const ulonglong2*)&As2[buf][kk * AP + 8 * iy + 4];
            ulonglong2 bp = *(const ulonglong2*)&Bs[buf][kk * BP + jx * 4];
            FFMA2(acc[0][0], aA.x, bp.x, acc[0][0]);
            FFMA2(acc[0][1], aA.x, bp.y, acc[0][1]);
            FFMA2(acc[1][0], aA.y, bp.x, acc[1][0]);
            FFMA2(acc[1][1], aA.y, bp.y, acc[1][1]);
            FFMA2(acc[2][0], aB.x, bp.x, acc[2][0]);
            FFMA2(acc[2][1], aB.x, bp.y, acc[2][1]);
            FFMA2(acc[3][0], aB.y, bp.x, acc[3][0]);
            FFMA2(acc[3][1], aB.y, bp.y, acc[3][1]);
        }
    }

    u64 bz0 = 0, bz1 = 0;
    if (z) {
        bz0 = *(const u64*)&b1[n0 + jx * 4];
        bz1 = *(const u64*)&b1[n0 + jx * 4 + 2];
    }

    #pragma unroll
    for (int i = 0; i < 4; i++) {
        ulonglong2 r;
        FADD2(r.x, acc[i][0], bz0);
        FADD2(r.y, acc[i][1], bz1);
        *(ulonglong2*)&dst[(m0 + iy * 4 + i) * FD + n0 + jx * 4] = r;
    }
}

// ---------------------------------------------------------------------------
// Kernel 2: decisions[b,i,j] = (sum_f relu(A[b,i,f]+C[b,j,f])*w2d[f] + b2d > 0)
//           ? -1e9 : 0
// 64i x 32j, 256 threads, per-thread 4i x 2j (one pair), f-chunk 32 with
// chunk-local partials (exact two-level fp32 order — precision-critical).
// relu exact identity: relu(s)*w = (s+|s|)*(w/2); |s| = and.b64 (alu pipe).
// 2-stage pipeline. Grid 16 x 8 x 2 = 256 blocks.
// ---------------------------------------------------------------------------
__global__ __launch_bounds__(256) void decisions_kernel(
    const float* __restrict__ W2, const float* __restrict__ b2)
{
    const int b  = blockIdx.z;
    const int i0 = blockIdx.y * 64;
    const int j0 = blockIdx.x * 32;
    const float* __restrict__ Ab = g_A + b * LQ * FD;
    const float* __restrict__ Cb = g_C + b * LQ * FD;

    __shared__ __align__(16) float As2[2][32 * AP];   // [f][2i] duplicated
    __shared__ __align__(16) float Cs[2][32 * CP];    // [f][j]
    __shared__ __align__(16) float2 ws2[FD];          // {w/2, w/2}

    const int t  = threadIdx.x;
    const int jx = t & 15, iy = t >> 4;
    const int rA = t >> 2, qA = t & 3;                // A fill: i-row, f-quad(+4h)
    const int rC = t >> 3, qC = t & 7;                // C fill: j-row, f-quad

    for (int f = t; f < FD; f += 256) {
        float w = 0.5f * (W2[2 * f + 1] - W2[2 * f]);
        ws2[f] = make_float2(w, w);
    }

    u64 acc[4] = {};
    float4 a0, a1, cc;

    a0 = *(const float4*)&Ab[(i0 + rA) * FD + qA * 4];
    a1 = *(const float4*)&Ab[(i0 + rA) * FD + (qA + 4) * 4];
    cc = *(const float4*)&Cb[(j0 + rC) * FD + qC * 4];

    #pragma unroll 1
    for (int c = 0; c < FD / 32; c++) {
        const int buf = c & 1;
        const int f0 = c * 32;
        {
            int q = qA;
            *(float2*)&As2[buf][(q * 4 + 0) * AP + 2 * rA] = make_float2(a0.x, a0.x);
            *(float2*)&As2[buf][(q * 4 + 1) * AP + 2 * rA] = make_float2(a0.y, a0.y);
            *(float2*)&As2[buf][(q * 4 + 2) * AP + 2 * rA] = make_float2(a0.z, a0.z);
            *(float2*)&As2[buf][(q * 4 + 3) * AP + 2 * rA] = make_float2(a0.w, a0.w);
            q = qA + 4;
            *(float2*)&As2[buf][(q * 4 + 0) * AP + 2 * rA] = make_float2(a1.x, a1.x);
            *(float2*)&As2[buf][(q * 4 + 1) * AP + 2 * rA] = make_float2(a1.y, a1.y);
            *(float2*)&As2[buf][(q * 4 + 2) * AP + 2 * rA] = make_float2(a1.z, a1.z);
            *(float2*)&As2[buf][(q * 4 + 3) * AP + 2 * rA] = make_float2(a1.w, a1.w);
            Cs[buf][(qC * 4 + 0) * CP + rC] = cc.x;
            Cs[buf][(qC * 4 + 1) * CP + rC] = cc.y;
            Cs[buf][(qC * 4 + 2) * CP + rC] = cc.z;
            Cs[buf][(qC * 4 + 3) * CP + rC] = cc.w;
        }
        __syncthreads();

        if (c + 1 < FD / 32) {
            int fn = (c + 1) * 32;
            a0 = *(const float4*)&Ab[(i0 + rA) * FD + fn + qA * 4];
            a1 = *(const float4*)&Ab[(i0 + rA) * FD + fn + (qA + 4) * 4];
            cc = *(const float4*)&Cb[(j0 + rC) * FD + fn + qC * 4];
        }

        u64 accC[4] = {};
        #pragma unroll
        for (int kk = 0; kk < 32; kk++) {
            ulonglong2 aA = *(const ulonglong2*)&As2[buf][kk * AP + 8 * iy];
            ulonglong2 aB = *(const ulonglong2*)&As2[buf][kk * AP + 8 * iy + 4];
            u64 cp = *(const u64*)&Cs[buf][kk * CP + jx * 2];
            u64 wd = *(const u64*)&ws2[f0 + kk];
            u64 ad[4] = {aA.x, aA.y, aB.x, aB.y};
            #pragma unroll
            for (int i = 0; i < 4; i++) {
                u64 s, s2;
                FADD2(s, ad[i], cp);
                s2 = s & ABS2_MASK;                 // |s|
                FADD2(s2, s, s2);                   // 2*relu(s), exact
                FFMA2(accC[i], s2, wd, accC[i]);    // *(w/2): exact scale
            }
        }
        #pragma unroll
        for (int i = 0; i < 4; i++)
            FADD2(acc[i], acc[i], accC[i]);
    }

    const float b2d = b2[1] - b2[0];
    float* Db = g_D + b * LQ * LQ;
    #pragma unroll
    for (int i = 0; i < 4; i++) {
        float2 p = unpk(acc[i]);
        float2 r = make_float2((p.x + b2d > 0.f) ? -1e9f : 0.f,
                               (p.y + b2d > 0.f) ? -1e9f : 0.f);
        *(float2*)&Db[(i0 + iy * 4 + i) * LQ + j0 + jx * 2] = r;
    }
}

// ---------------------------------------------------------------------------
// Kernel 3: out[b,n,i,j] = dot(q[b,n,i,:], k[b,n,j,:]) * 0.125 + D[b,i,j]
// 64i x 64j, 256 threads, per-thread 4i x 4j, d-chunk 16, 2-stage pipeline.
// Grid 8 x 8 x 16 = 1024 blocks.
// ---------------------------------------------------------------------------
__global__ __launch_bounds__(256) void attn_kernel(
    const float* __restrict__ q, const float* __restrict__ k,
    float* __restrict__ out)
{
    const int bn = blockIdx.z;          // b*NH + n
    const int b  = bn >> 3;
    const int i0 = blockIdx.y * 64;
    const int j0 = blockIdx.x * 64;
    const float* __restrict__ Q = q + bn * LQ * DK;
    const float* __restrict__ K = k + bn * LQ * DK;

    __shared__ __align__(16) float Qs2[2][16 * AP];   // [d][2i] duplicated
    __shared__ __align__(16) float Ks[2][16 * BP];    // [d][j]

    const int t  = threadIdx.x;
    const int jx = t & 15, iy = t >> 4;
    const int rA = t >> 2, qA = t & 3;                // fills: row, d-quad

    u64 acc[4][2] = {};
    float4 vq, vk;

    vq = *(const float4*)&Q[(i0 + rA) * DK + qA * 4];
    vk = *(const float4*)&K[(j0 + rA) * DK + qA * 4];

    #pragma unroll 1
    for (int c = 0; c < DK / 16; c++) {
        const int buf = c & 1;
        *(float2*)&Qs2[buf][(qA * 4 + 0) * AP + 2 * rA] = make_float2(vq.x, vq.x);
        *(float2*)&Qs2[buf][(qA * 4 + 1) * AP + 2 * rA] = make_float2(vq.y, vq.y);
        *(float2*)&Qs2[buf][(qA * 4 + 2) * AP + 2 * rA] = make_float2(vq.z, vq.z);
        *(float2*)&Qs2[buf][(qA * 4 + 3) * AP + 2 * rA] = make_float2(vq.w, vq.w);
        Ks[buf][(qA * 4 + 0) * BP + rA] = vk.x;
        Ks[buf][(qA * 4 + 1) * BP + rA] = vk.y;
        Ks[buf][(qA * 4 + 2) * BP + rA] = vk.z;
        Ks[buf][(qA * 4 + 3) * BP + rA] = vk.w;
        __syncthreads();

        if (c + 1 < DK / 16) {
            int d0 = (c + 1) * 16;
            vq = *(const float4*)&Q[(i0 + rA) * DK + d0 + qA * 4];
            vk = *(const float4*)&K[(j0 + rA) * DK + d0 + qA * 4];
        }

        #pragma unroll
        for (int kk = 0; kk < 16; kk++) {
            ulonglong2 aA = *(const ulonglong2*)&Qs2[buf][kk * AP + 8 * iy];
            ulonglong2 aB = *(const ulonglong2*)&Qs2[buf][kk * AP + 8 * iy + 4];
            ulonglong2 bp = *(const ulonglong2*)&Ks[buf][kk * BP + jx * 4];
            FFMA2(acc[0][0], aA.x, bp.x, acc[0][0]);
            FFMA2(acc[0][1], aA.x, bp.y, acc[0][1]);
            FFMA2(acc[1][0], aA.y, bp.x, acc[1][0]);
            FFMA2(acc[1][1], aA.y, bp.y, acc[1][1]);
            FFMA2(acc[2][0], aB.x, bp.x, acc[2][0]);
            FFMA2(acc[2][1], aB.x, bp.y, acc[2][1]);
            FFMA2(acc[3][0], aB.y, bp.x, acc[3][0]);
            FFMA2(acc[3][1], aB.y, bp.y, acc[3][1]);
        }
    }

    const float* Db = g_D + b * LQ * LQ;
    float* O = out + bn * LQ * LQ;
    const u64 e2 = EIGHTH2;
    #pragma unroll
    for (int i = 0; i < 4; i++) {
        int row = i0 + iy * 4 + i;
        ulonglong2 dv = *(const ulonglong2*)&Db[row * LQ + j0 + jx * 4];
        ulonglong2 r;
        FFMA2(r.x, acc[i][0], e2, dv.x);            // qk*0.125 + D, packed
        FFMA2(r.y, acc[i][1], e2, dv.y);
        *(ulonglong2*)&O[row * LQ + j0 + jx * 4] = r;
    }
}

// ---------------------------------------------------------------------------
// Inputs (metadata order): q, k, d0, d1, W1, b1, W2, b2
// ---------------------------------------------------------------------------
extern "C" void kernel_launch(void* const* d_in, const int* in_sizes, int n_in,
                              void* d_out, int out_size)
{
    const float* q  = (const float*)d_in[0];   // [2,8,512,64]
    const float* k  = (const float*)d_in[1];   // [2,8,512,64]
    const float* d0 = (const float*)d_in[2];   // [2,512,256]
    const float* d1 = (const float*)d_in[3];   // [2,512,256]
    const float* W1 = (const float*)d_in[4];   // [512,512]
    const float* b1 = (const float*)d_in[5];   // [512]
    const float* W2 = (const float*)d_in[6];   // [512,2]
    const float* b2 = (const float*)d_in[7];   // [2]
    float* out = (float*)d_out;                // [2,8,512,512]

    (void)in_sizes; (void)n_in; (void)out_size;

    gemm_ac_kernel  <<<dim3(FD / 64, (NB * LQ) / 64, 2),   256>>>(d1, d0, W1, b1);
    decisions_kernel<<<dim3(LQ / 32, LQ / 64, NB),         256>>>(W2, b2);
    attn_kernel     <<<dim3(LQ / 64, LQ / 64, NB * NH),    256>>>(q, k, out);
}